// round 13
// baseline (speedup 1.0000x reference)
#include <cuda_runtime.h>
#include <cuda_bf16.h>
#include <cuda_fp16.h>
#include <cstdint>

// Problem constants
#define BB 64
#define NN 64
#define CC 8
#define FF 256
#define KDIM 2048   // C*F
#define ODIM 2048   // OC*OF
#define MROWS 4160  // B + B*N rows of Z
#define MPAD 4224   // padded to 44*96 (= 33*128)

// Scratch (device globals; no dynamic allocation allowed)
__device__ float g_s1[BB];
__device__ float g_wraw[BB * NN];
__device__ float g_t[BB * KDIM];
// adj single fp16 (written directly by k_adj)
__device__ __half g_adjh[(size_t)BB * CC * FF * FF];  // 67 MB
// A-operand for znx GEMM: per b, 80 rows (64 neighbors, x, 15 pad), single fp16
__device__ __half g_nxh[(size_t)BB * 80 * KDIM];
// single fp16 Z and W for the big GEMM
__device__ __half g_Zh[(size_t)MPAD * KDIM];
__device__ __half g_Wh[(size_t)ODIM * KDIM];

__device__ __forceinline__ float blockReduce256(float v) {
    __shared__ float sh[8];
    #pragma unroll
    for (int o = 16; o > 0; o >>= 1) v += __shfl_down_sync(0xffffffffu, v, o);
    int lane = threadIdx.x & 31, wid = threadIdx.x >> 5;
    if (lane == 0) sh[wid] = v;
    __syncthreads();
    if (wid == 0) {
        v = (lane < 8) ? sh[lane] : 0.f;
        #pragma unroll
        for (int o = 4; o > 0; o >>= 1) v += __shfl_down_sync(0xffffffffu, v, o);
    }
    return v;
}

__device__ __forceinline__ float sqrt_approx(float v) {
    float r;
    asm("sqrt.approx.f32 %0, %1;" : "=f"(r) : "f"(v));
    return r;
}
__device__ __forceinline__ float rcp_approx(float v) {
    float r;
    asm("rcp.approx.f32 %0, %1;" : "=f"(r) : "f"(v));
    return r;
}

// K1 (merged): wsum (per-block, smem) + cvt_nx (blocks 0..5119)
//              + cvt_W (5120..7167) + Zh pad zero (7168..7231)
#define NB_NX   (80 * BB)             // 5120
#define NB_PREP (NB_NX + ODIM + (MPAD - MROWS))

__global__ void k_prep(const float* __restrict__ x, const float* __restrict__ nb,
                       const float* __restrict__ W1, const float* __restrict__ W2,
                       const float* __restrict__ Wc) {
    int bid = blockIdx.x;
    int tf = threadIdx.x;
    int c0 = tf * 8;
    if (bid < NB_NX) {
        // per-block W1/W2 column sums (replaces separate k_wsum launch)
        __shared__ float sws[2][FF];
        float wa = 0.f, wb = 0.f;
        #pragma unroll
        for (int k = 0; k < CC; k++) { wa += W1[k * FF + tf]; wb += W2[k * FF + tf]; }
        sws[0][tf] = wa; sws[1][tf] = wb;
        __syncthreads();
        // ---- cvt_nx: build 80-row A operand + fused s1/wraw reductions ----
        int r = bid % 80, b = bid / 80;
        size_t orow = ((size_t)b * 80 + r) * KDIM + c0;
        __align__(16) __half h[8];
        if (r <= 64) {
            const float* src = (r < 64) ? nb + ((size_t)b * NN + r) * KDIM
                                        : x + (size_t)b * KDIM;
            const float4* p = (const float4*)(src + c0);
            float4 v0 = p[0], v1 = p[1];
            float vv[8] = {v0.x, v0.y, v0.z, v0.w, v1.x, v1.y, v1.z, v1.w};
            #pragma unroll
            for (int i = 0; i < 8; i++) h[i] = __float2half_rn(vv[i]);
            *(uint4*)(g_nxh + orow) = *(uint4*)&h[0];
            const float* ws = sws[(r < 64) ? 1 : 0];
            float dot = 0.f;
            #pragma unroll
            for (int i = 0; i < 8; i++) dot += vv[i] * ws[(c0 + i) & (FF - 1)];
            dot = blockReduce256(dot);
            if (tf == 0) {
                if (r < 64) g_wraw[b * NN + r] = dot;
                else        g_s1[b] = dot;
            }
        } else {
            #pragma unroll
            for (int i = 0; i < 8; i++) h[i] = __float2half_rn(0.f);
            *(uint4*)(g_nxh + orow) = *(uint4*)&h[0];
        }
    } else if (bid < NB_NX + ODIM) {
        // ---- cvt_W: W -> single fp16 ----
        size_t row = bid - NB_NX;
        const float4* p = (const float4*)(Wc + row * KDIM + c0);
        float4 v0 = p[0], v1 = p[1];
        float vv[8] = {v0.x, v0.y, v0.z, v0.w, v1.x, v1.y, v1.z, v1.w};
        __align__(16) __half h[8];
        #pragma unroll
        for (int i = 0; i < 8; i++) h[i] = __float2half_rn(vv[i]);
        *(uint4*)(g_Wh + row * KDIM + c0) = *(uint4*)&h[0];
    } else {
        // ---- zero Zh pad rows ----
        size_t row = MROWS + (bid - NB_NX - ODIM);
        *(uint4*)(g_Zh + row * KDIM + c0) = make_uint4(0, 0, 0, 0);
    }
}

// K3: t[b,c,d] = sum_n nxh[b,n,c,d] * (s1[b]*wraw[b,n]); half2 vectorized
__global__ void k_t() {
    int b = blockIdx.x >> 2;
    int r0 = ((blockIdx.x & 3) << 9) | (threadIdx.x << 1);
    __shared__ float sw[NN];
    if (threadIdx.x < NN)
        sw[threadIdx.x] = g_wraw[b * NN + threadIdx.x] * g_s1[b];
    __syncthreads();
    const __half2* p = (const __half2*)(g_nxh + (size_t)b * 80 * KDIM + r0);
    float2 acc = make_float2(0.f, 0.f);
    #pragma unroll 8
    for (int n = 0; n < NN; n++) {
        float2 f = __half22float2(p[(size_t)n * (KDIM / 2)]);
        acc.x += f.x * sw[n];
        acc.y += f.y * sw[n];
    }
    *(float2*)(g_t + (size_t)b * KDIM + r0) = acc;
}

// K4: adj[b,c,a,d] = sgnroot(x_a t_d + x_d t_a) / (sum_c |sgnroot| + 1e-7)
// Issue-optimized: sqrt.approx + copysign + rcp.approx + half2 cvt.
__global__ void k_adj(const float* __restrict__ x) {
    int a0 = blockIdx.x << 2, b = blockIdx.y;
    __shared__ float sxa[CC][4], sta[CC][4];
    int t = threadIdx.x;
    if (t < 32)      sxa[t >> 2][t & 3] = x[b * KDIM + (t >> 2) * FF + a0 + (t & 3)];
    else if (t < 64) {
        int q = t - 32;
        sta[q >> 2][q & 3] = g_t[b * KDIM + (q >> 2) * FF + a0 + (q & 3)];
    }
    __syncthreads();
    int al = t >> 6;            // 0..3 -> which a in the group
    int d0 = (t & 63) << 2;     // 0..252, 4 d's per thread
    float gg[CC][4];
    float den[4] = {1e-7f, 1e-7f, 1e-7f, 1e-7f};
    #pragma unroll
    for (int c = 0; c < CC; c++) {
        float xa = sxa[c][al], ta = sta[c][al];
        float4 xd = *(const float4*)(x + b * KDIM + c * FF + d0);
        float4 td = *(const float4*)(g_t + b * KDIM + c * FF + d0);
        float fv[4] = {xa * td.x + xd.x * ta, xa * td.y + xd.y * ta,
                       xa * td.z + xd.z * ta, xa * td.w + xd.w * ta};
        #pragma unroll
        for (int i = 0; i < 4; i++) {
            float fa = fv[i];
            float sq = sqrt_approx(fmaxf(fabsf(fa), 1e-8f));
            den[i] += sq;                       // |g| == sq (non-negative)
            gg[c][i] = __int_as_float(
                (__float_as_int(sq) & 0x7fffffff) | (__float_as_int(fa) & 0x80000000));
        }
    }
    float inv[4];
    #pragma unroll
    for (int i = 0; i < 4; i++) inv[i] = rcp_approx(den[i]);
    int a = a0 + al;
    #pragma unroll
    for (int c = 0; c < CC; c++) {
        __half2 p0 = __float22half2_rn(make_float2(gg[c][0] * inv[0], gg[c][1] * inv[1]));
        __half2 p1 = __float22half2_rn(make_float2(gg[c][2] * inv[2], gg[c][3] * inv[3]));
        uint2 pk = make_uint2(*(uint32_t*)&p0, *(uint32_t*)&p1);
        *(uint2*)(g_adjh + (((size_t)(b * CC + c) * FF + a) * FF + d0)) = pk;
    }
}

// ---------- warp-MMA helpers (sm_80+ PTX only) ----------
__device__ __forceinline__ uint32_t smem_u32(const void* p) {
    uint32_t a;
    asm("{ .reg .u64 t; cvta.to.shared.u64 t, %1; cvt.u32.u64 %0, t; }"
        : "=r"(a) : "l"(p));
    return a;
}
__device__ __forceinline__ void cp16(uint32_t s, const void* g) {
    asm volatile("cp.async.cg.shared.global [%0], [%1], 16;" :: "r"(s), "l"(g) : "memory");
}
__device__ __forceinline__ void ldsm4(uint32_t* r, uint32_t addr) {
    asm volatile("ldmatrix.sync.aligned.m8n8.x4.shared.b16 {%0,%1,%2,%3}, [%4];"
                 : "=r"(r[0]), "=r"(r[1]), "=r"(r[2]), "=r"(r[3]) : "r"(addr));
}
__device__ __forceinline__ void mma16816h(float* c, const uint32_t* a, const uint32_t* b) {
    asm volatile(
        "mma.sync.aligned.m16n8k16.row.col.f32.f16.f16.f32 "
        "{%0,%1,%2,%3}, {%4,%5,%6,%7}, {%8,%9}, {%0,%1,%2,%3};"
        : "+f"(c[0]), "+f"(c[1]), "+f"(c[2]), "+f"(c[3])
        : "r"(a[0]), "r"(a[1]), "r"(a[2]), "r"(a[3]), "r"(b[0]), "r"(b[1]));
}

// ====================== K5: fused zn+zx tensor GEMM ======================
// Per (b,c): Z[n=80, a=256] = Nh[80x256k] @ Ah[a=256 x 256k]^T  (both single fp16)
// 512 threads / 16 warps: each warp covers full M=80 (5 m16 frags) x N=16.
// K-chunk 32, 3-stage. Occupancy-driven restructure (was 8 warps @ 170 regs).
#define ZNST 3
#define ZROWB 80
#define ZA_TILE (80 * ZROWB)       // 6400
#define ZB_TILE (256 * ZROWB)      // 20480
#define ZSTAGE (ZA_TILE + ZB_TILE) // 26880
#define ZNX_SMEM (ZNST * ZSTAGE)   // 80640

__device__ __forceinline__ void znx_load(char* smbase, int st, int kc,
                                         int tid, int b, int c) {
    uint32_t so = smem_u32(smbase) + st * ZSTAGE;
    int kb = kc << 5;
    // A: 80 rows x 4 segs = 320 loads (threads 0..319)
    if (tid < 320) {
        int r = tid >> 2, s = tid & 3;
        size_t g = ((size_t)b * 80 + r) * KDIM + c * FF + kb + s * 8;
        cp16(so + r * ZROWB + (s << 4), g_nxh + g);
    }
    // B: 256 rows x 4 segs = 1024 loads (2 per thread)
    #pragma unroll
    for (int t = 0; t < 2; t++) {
        int idx = tid + (t << 9);
        int a = idx >> 2, s = idx & 3;
        size_t g = (((size_t)(b * CC + c)) * FF + a) * FF + kb + s * 8;
        cp16(so + ZA_TILE + a * ZROWB + (s << 4), g_adjh + g);
    }
}

__global__ __launch_bounds__(512, 1) void k_znx() {
    extern __shared__ char sm[];
    uint32_t sbase = smem_u32(sm);
    int tid = threadIdx.x;
    int lane = tid & 31, wid = tid >> 5;
    int c = blockIdx.x, b = blockIdx.y;
    int wn = wid << 4;             // 16 warps x N=16

    float acc[5][2][4];
    #pragma unroll
    for (int i = 0; i < 5; i++)
        #pragma unroll
        for (int j = 0; j < 2; j++)
            #pragma unroll
            for (int q = 0; q < 4; q++) acc[i][j][q] = 0.f;

    int a_row = ((lane >> 3) & 1) * 8 + (lane & 7);
    int a_kof = (lane >> 4) * 8;
    int b_row = wn + ((lane >> 4) & 1) * 8 + (lane & 7);
    int b_kof = ((lane >> 3) & 1) * 8;

    znx_load(sm, 0, 0, tid, b, c);
    asm volatile("cp.async.commit_group;" ::: "memory");
    znx_load(sm, 1, 1, tid, b, c);
    asm volatile("cp.async.commit_group;" ::: "memory");

    for (int kc = 0; kc < 8; kc++) {
        asm volatile("cp.async.wait_group 1;" ::: "memory");
        __syncthreads();
        if (kc + 2 < 8) znx_load(sm, (kc + 2) % ZNST, kc + 2, tid, b, c);
        asm volatile("cp.async.commit_group;" ::: "memory");

        uint32_t sA = sbase + (kc % ZNST) * ZSTAGE;
        uint32_t sB = sA + ZA_TILE;
        #pragma unroll
        for (int kk = 0; kk < 2; kk++) {
            int kb = kk << 4;
            uint32_t ah[5][4], bh[4];
            uint32_t aofs = a_row * ZROWB + (kb + a_kof) * 2;
            #pragma unroll
            for (int mt = 0; mt < 5; mt++)
                ldsm4(ah[mt], sA + aofs + mt * 16 * ZROWB);
            uint32_t bofs = b_row * ZROWB + (kb + b_kof) * 2;
            ldsm4(bh, sB + bofs);
            #pragma unroll
            for (int mt = 0; mt < 5; mt++)
                #pragma unroll
                for (int j = 0; j < 2; j++)
                    mma16816h(acc[mt][j], ah[mt], &bh[j * 2]);
        }
        __syncthreads();
    }

    // epilogue: rows = n (x at n==64), cols = a; write single fp16 Zh
    #pragma unroll
    for (int mt = 0; mt < 5; mt++) {
        #pragma unroll
        for (int half = 0; half < 2; half++) {
            int r = mt * 16 + (lane >> 2) + half * 8;
            int zr;
            if (r < 64)       zr = 64 + b * NN + r;
            else if (r == 64) zr = b;
            else continue;
            #pragma unroll
            for (int j = 0; j < 2; j++) {
                int col = c * FF + wn + j * 8 + (lane & 3) * 2;
                *(__half2*)(g_Zh + (size_t)zr * KDIM + col) =
                    __halves2half2(__float2half_rn(acc[mt][j][half * 2]),
                                   __float2half_rn(acc[mt][j][half * 2 + 1]));
            }
        }
    }
}

// ====================== K7: big GEMM, 96x128 tiles, occ 2 (proven) ======================
#define NST 5
#define ROWB 80
#define GM 96
#define A_TILE_B (GM * ROWB)          // 7680
#define B_TILE_B (128 * ROWB)         // 10240
#define STAGE_B (A_TILE_B + B_TILE_B) // 17920
#define GEMM_SMEM (NST * STAGE_B)     // 89600

__device__ __forceinline__ void g_load_stage(char* smembase, int st, int kc,
                                             int tid, int m0, int n0) {
    uint32_t so_base = smem_u32(smembase) + st * STAGE_B;
    {
        int row = tid >> 2, seg = tid & 3;
        size_t gA = (size_t)(m0 + row) * KDIM + (kc << 5) + (seg << 3);
        cp16(so_base + row * ROWB + (seg << 4), g_Zh + gA);
        if (tid < 128) {
            int idx = tid + 256;
            int row2 = idx >> 2, seg2 = idx & 3;
            size_t gA2 = (size_t)(m0 + row2) * KDIM + (kc << 5) + (seg2 << 3);
            cp16(so_base + row2 * ROWB + (seg2 << 4), g_Zh + gA2);
        }
    }
    #pragma unroll
    for (int t = 0; t < 2; t++) {
        int idx = tid + (t << 8);
        int row = idx >> 2, seg = idx & 3;
        size_t gB = (size_t)(n0 + row) * KDIM + (kc << 5) + (seg << 3);
        cp16(so_base + A_TILE_B + row * ROWB + (seg << 4), g_Wh + gB);
    }
}

__global__ __launch_bounds__(256, 2) void k_gemm_mma(float* __restrict__ out) {
    extern __shared__ char sm[];
    uint32_t sbase = smem_u32(sm);
    int tid = threadIdx.x;
    int lane = tid & 31, wid = tid >> 5;
    int m0 = blockIdx.y * GM, n0 = blockIdx.x << 7;
    int wm = (wid >> 2) * 48;       // 0 / 48 (3 m16 frags each)
    int wn = (wid & 3) << 5;

    float c[3][4][4];
    #pragma unroll
    for (int i = 0; i < 3; i++)
        #pragma unroll
        for (int j = 0; j < 4; j++)
            #pragma unroll
            for (int q = 0; q < 4; q++) c[i][j][q] = 0.f;

    int a_row = wm + ((lane >> 3) & 1) * 8 + (lane & 7);
    int a_kof = (lane >> 4) * 8;
    int b_row = wn + ((lane >> 4) & 1) * 8 + (lane & 7);
    int b_kof = ((lane >> 3) & 1) * 8;

    #pragma unroll
    for (int st = 0; st < 4; st++) {
        g_load_stage(sm, st, st, tid, m0, n0);
        asm volatile("cp.async.commit_group;" ::: "memory");
    }

    for (int kc = 0; kc < 64; kc++) {
        asm volatile("cp.async.wait_group 3;" ::: "memory");
        __syncthreads();
        if (kc + 4 < 64) g_load_stage(sm, (kc + 4) % NST, kc + 4, tid, m0, n0);
        asm volatile("cp.async.commit_group;" ::: "memory");

        uint32_t sA = sbase + (kc % NST) * STAGE_B;
        uint32_t sB = sA + A_TILE_B;
        #pragma unroll
        for (int kk = 0; kk < 2; kk++) {
            int kb = kk << 4;
            uint32_t ah[3][4], bh[2][4];
            uint32_t aofs = a_row * ROWB + (kb + a_kof) * 2;
            #pragma unroll
            for (int mt = 0; mt < 3; mt++)
                ldsm4(ah[mt], sA + aofs + mt * 16 * ROWB);
            uint32_t bofs = b_row * ROWB + (kb + b_kof) * 2;
            #pragma unroll
            for (int np = 0; np < 2; np++)
                ldsm4(bh[np], sB + bofs + np * 16 * ROWB);
            #pragma unroll
            for (int mt = 0; mt < 3; mt++)
                #pragma unroll
                for (int j = 0; j < 4; j++)
                    mma16816h(c[mt][j], ah[mt], &bh[j >> 1][(j & 1) * 2]);
        }
        __syncthreads();
    }

    #pragma unroll
    for (int mt = 0; mt < 3; mt++) {
        int r0 = m0 + wm + mt * 16 + (lane >> 2);
        #pragma unroll
        for (int j = 0; j < 4; j++) {
            int col = n0 + wn + j * 8 + (lane & 3) * 2;
            if (r0 < MROWS)
                *(float2*)(out + (size_t)r0 * ODIM + col) =
                    make_float2(c[mt][j][0], c[mt][j][1]);
            if (r0 + 8 < MROWS)
                *(float2*)(out + (size_t)(r0 + 8) * ODIM + col) =
                    make_float2(c[mt][j][2], c[mt][j][3]);
        }
    }
}

extern "C" void kernel_launch(void* const* d_in, const int* in_sizes, int n_in,
                              void* d_out, int out_size) {
    const float* x  = (const float*)d_in[0];  // (64,8,256)
    const float* nb = (const float*)d_in[1];  // (64,64,8,256)
    const float* W1 = (const float*)d_in[2];  // (8,256)
    const float* W2 = (const float*)d_in[3];  // (8,256)
    const float* Wc = (const float*)d_in[4];  // (2048,8,256)
    float* out = (float*)d_out;

    static bool attr_set = false;
    if (!attr_set) {
        cudaFuncSetAttribute(k_gemm_mma, cudaFuncAttributeMaxDynamicSharedMemorySize,
                             GEMM_SMEM);
        cudaFuncSetAttribute(k_znx, cudaFuncAttributeMaxDynamicSharedMemorySize,
                             ZNX_SMEM);
        attr_set = true;
    }

    k_prep<<<NB_PREP, 256>>>(x, nb, W1, W2, Wc);
    k_t<<<256, 256>>>();
    k_adj<<<dim3(FF / 4, BB), 256>>>(x);
    k_znx<<<dim3(CC, BB), 512, ZNX_SMEM>>>();
    k_gemm_mma<<<dim3(16, MPAD / GM), 256, GEMM_SMEM>>>(out);
}

// round 14
// speedup vs baseline: 1.0216x; 1.0216x over previous
#include <cuda_runtime.h>
#include <cuda_bf16.h>
#include <cuda_fp16.h>
#include <cstdint>

// Problem constants
#define BB 64
#define NN 64
#define CC 8
#define FF 256
#define KDIM 2048   // C*F
#define ODIM 2048   // OC*OF
#define MROWS 4160  // B + B*N rows of Z
#define MPAD 4224   // padded to 44*96 (= 33*128)

// Scratch (device globals; no dynamic allocation allowed)
__device__ float g_s1[BB];
__device__ float g_wraw[BB * NN];
__device__ float g_t[BB * KDIM];
// adj single fp16 (written directly by k_adj)
__device__ __half g_adjh[(size_t)BB * CC * FF * FF];  // 67 MB
// A-operand for znx GEMM: per b, 80 rows (64 neighbors, x, 15 pad), single fp16
__device__ __half g_nxh[(size_t)BB * 80 * KDIM];
// single fp16 Z and W for the big GEMM
__device__ __half g_Zh[(size_t)MPAD * KDIM];
__device__ __half g_Wh[(size_t)ODIM * KDIM];

__device__ __forceinline__ float blockReduce256(float v) {
    __shared__ float sh[8];
    #pragma unroll
    for (int o = 16; o > 0; o >>= 1) v += __shfl_down_sync(0xffffffffu, v, o);
    int lane = threadIdx.x & 31, wid = threadIdx.x >> 5;
    if (lane == 0) sh[wid] = v;
    __syncthreads();
    if (wid == 0) {
        v = (lane < 8) ? sh[lane] : 0.f;
        #pragma unroll
        for (int o = 4; o > 0; o >>= 1) v += __shfl_down_sync(0xffffffffu, v, o);
    }
    return v;
}

__device__ __forceinline__ float sqrt_approx(float v) {
    float r;
    asm("sqrt.approx.f32 %0, %1;" : "=f"(r) : "f"(v));
    return r;
}
__device__ __forceinline__ float rcp_approx(float v) {
    float r;
    asm("rcp.approx.f32 %0, %1;" : "=f"(r) : "f"(v));
    return r;
}

// K1 (merged): wsum (per-block, smem) + cvt_nx (blocks 0..5119)
//              + cvt_W (5120..7167) + Zh pad zero (7168..7231)
#define NB_NX   (80 * BB)             // 5120
#define NB_PREP (NB_NX + ODIM + (MPAD - MROWS))

__global__ void k_prep(const float* __restrict__ x, const float* __restrict__ nb,
                       const float* __restrict__ W1, const float* __restrict__ W2,
                       const float* __restrict__ Wc) {
    int bid = blockIdx.x;
    int tf = threadIdx.x;
    int c0 = tf * 8;
    if (bid < NB_NX) {
        // per-block W1/W2 column sums (replaces separate k_wsum launch)
        __shared__ float sws[2][FF];
        float wa = 0.f, wb = 0.f;
        #pragma unroll
        for (int k = 0; k < CC; k++) { wa += W1[k * FF + tf]; wb += W2[k * FF + tf]; }
        sws[0][tf] = wa; sws[1][tf] = wb;
        __syncthreads();
        // ---- cvt_nx: build 80-row A operand + fused s1/wraw reductions ----
        int r = bid % 80, b = bid / 80;
        size_t orow = ((size_t)b * 80 + r) * KDIM + c0;
        __align__(16) __half h[8];
        if (r <= 64) {
            const float* src = (r < 64) ? nb + ((size_t)b * NN + r) * KDIM
                                        : x + (size_t)b * KDIM;
            const float4* p = (const float4*)(src + c0);
            float4 v0 = p[0], v1 = p[1];
            float vv[8] = {v0.x, v0.y, v0.z, v0.w, v1.x, v1.y, v1.z, v1.w};
            #pragma unroll
            for (int i = 0; i < 8; i++) h[i] = __float2half_rn(vv[i]);
            *(uint4*)(g_nxh + orow) = *(uint4*)&h[0];
            const float* ws = sws[(r < 64) ? 1 : 0];
            float dot = 0.f;
            #pragma unroll
            for (int i = 0; i < 8; i++) dot += vv[i] * ws[(c0 + i) & (FF - 1)];
            dot = blockReduce256(dot);
            if (tf == 0) {
                if (r < 64) g_wraw[b * NN + r] = dot;
                else        g_s1[b] = dot;
            }
        } else {
            #pragma unroll
            for (int i = 0; i < 8; i++) h[i] = __float2half_rn(0.f);
            *(uint4*)(g_nxh + orow) = *(uint4*)&h[0];
        }
    } else if (bid < NB_NX + ODIM) {
        // ---- cvt_W: W -> single fp16 ----
        size_t row = bid - NB_NX;
        const float4* p = (const float4*)(Wc + row * KDIM + c0);
        float4 v0 = p[0], v1 = p[1];
        float vv[8] = {v0.x, v0.y, v0.z, v0.w, v1.x, v1.y, v1.z, v1.w};
        __align__(16) __half h[8];
        #pragma unroll
        for (int i = 0; i < 8; i++) h[i] = __float2half_rn(vv[i]);
        *(uint4*)(g_Wh + row * KDIM + c0) = *(uint4*)&h[0];
    } else {
        // ---- zero Zh pad rows ----
        size_t row = MROWS + (bid - NB_NX - ODIM);
        *(uint4*)(g_Zh + row * KDIM + c0) = make_uint4(0, 0, 0, 0);
    }
}

// K3: t[b,c,d] = sum_n nxh[b,n,c,d] * (s1[b]*wraw[b,n]); half2 vectorized
__global__ void k_t() {
    int b = blockIdx.x >> 2;
    int r0 = ((blockIdx.x & 3) << 9) | (threadIdx.x << 1);
    __shared__ float sw[NN];
    if (threadIdx.x < NN)
        sw[threadIdx.x] = g_wraw[b * NN + threadIdx.x] * g_s1[b];
    __syncthreads();
    const __half2* p = (const __half2*)(g_nxh + (size_t)b * 80 * KDIM + r0);
    float2 acc = make_float2(0.f, 0.f);
    #pragma unroll 8
    for (int n = 0; n < NN; n++) {
        float2 f = __half22float2(p[(size_t)n * (KDIM / 2)]);
        acc.x += f.x * sw[n];
        acc.y += f.y * sw[n];
    }
    *(float2*)(g_t + (size_t)b * KDIM + r0) = acc;
}

// K4: adj[b,c,a,d] = sgnroot(x_a t_d + x_d t_a) / (sum_c |sgnroot| + 1e-7)
// Issue-optimized: sqrt.approx + copysign + rcp.approx + half2 cvt.
__global__ void k_adj(const float* __restrict__ x) {
    int a0 = blockIdx.x << 2, b = blockIdx.y;
    __shared__ float sxa[CC][4], sta[CC][4];
    int t = threadIdx.x;
    if (t < 32)      sxa[t >> 2][t & 3] = x[b * KDIM + (t >> 2) * FF + a0 + (t & 3)];
    else if (t < 64) {
        int q = t - 32;
        sta[q >> 2][q & 3] = g_t[b * KDIM + (q >> 2) * FF + a0 + (q & 3)];
    }
    __syncthreads();
    int al = t >> 6;            // 0..3 -> which a in the group
    int d0 = (t & 63) << 2;     // 0..252, 4 d's per thread
    float gg[CC][4];
    float den[4] = {1e-7f, 1e-7f, 1e-7f, 1e-7f};
    #pragma unroll
    for (int c = 0; c < CC; c++) {
        float xa = sxa[c][al], ta = sta[c][al];
        float4 xd = *(const float4*)(x + b * KDIM + c * FF + d0);
        float4 td = *(const float4*)(g_t + b * KDIM + c * FF + d0);
        float fv[4] = {xa * td.x + xd.x * ta, xa * td.y + xd.y * ta,
                       xa * td.z + xd.z * ta, xa * td.w + xd.w * ta};
        #pragma unroll
        for (int i = 0; i < 4; i++) {
            float fa = fv[i];
            float sq = sqrt_approx(fmaxf(fabsf(fa), 1e-8f));
            den[i] += sq;                       // |g| == sq (non-negative)
            gg[c][i] = __int_as_float(
                (__float_as_int(sq) & 0x7fffffff) | (__float_as_int(fa) & 0x80000000));
        }
    }
    float inv[4];
    #pragma unroll
    for (int i = 0; i < 4; i++) inv[i] = rcp_approx(den[i]);
    int a = a0 + al;
    #pragma unroll
    for (int c = 0; c < CC; c++) {
        __half2 p0 = __float22half2_rn(make_float2(gg[c][0] * inv[0], gg[c][1] * inv[1]));
        __half2 p1 = __float22half2_rn(make_float2(gg[c][2] * inv[2], gg[c][3] * inv[3]));
        uint2 pk = make_uint2(*(uint32_t*)&p0, *(uint32_t*)&p1);
        *(uint2*)(g_adjh + (((size_t)(b * CC + c) * FF + a) * FF + d0)) = pk;
    }
}

// ---------- warp-MMA helpers (sm_80+ PTX only) ----------
__device__ __forceinline__ uint32_t smem_u32(const void* p) {
    uint32_t a;
    asm("{ .reg .u64 t; cvta.to.shared.u64 t, %1; cvt.u32.u64 %0, t; }"
        : "=r"(a) : "l"(p));
    return a;
}
__device__ __forceinline__ void cp16(uint32_t s, const void* g) {
    asm volatile("cp.async.cg.shared.global [%0], [%1], 16;" :: "r"(s), "l"(g) : "memory");
}
__device__ __forceinline__ void ldsm4(uint32_t* r, uint32_t addr) {
    asm volatile("ldmatrix.sync.aligned.m8n8.x4.shared.b16 {%0,%1,%2,%3}, [%4];"
                 : "=r"(r[0]), "=r"(r[1]), "=r"(r[2]), "=r"(r[3]) : "r"(addr));
}
__device__ __forceinline__ void mma16816h(float* c, const uint32_t* a, const uint32_t* b) {
    asm volatile(
        "mma.sync.aligned.m16n8k16.row.col.f32.f16.f16.f32 "
        "{%0,%1,%2,%3}, {%4,%5,%6,%7}, {%8,%9}, {%0,%1,%2,%3};"
        : "+f"(c[0]), "+f"(c[1]), "+f"(c[2]), "+f"(c[3])
        : "r"(a[0]), "r"(a[1]), "r"(a[2]), "r"(a[3]), "r"(b[0]), "r"(b[1]));
}

// ====================== K5: fused zn+zx tensor GEMM ======================
// Per (b,c): Z[n=80, a=256] = Nh[80x256k] @ Ah[a=256 x 256k]^T  (both single fp16)
// REVERTED to 8 warps / 256 threads (R11 known-good); warp = M80 x N32.
// Pipeline deepened 3 -> 4 stages (107.5 KB smem, occ 1) to hide DRAM latency.
#define ZNST 4
#define ZROWB 80
#define ZA_TILE (80 * ZROWB)       // 6400
#define ZB_TILE (256 * ZROWB)      // 20480
#define ZSTAGE (ZA_TILE + ZB_TILE) // 26880
#define ZNX_SMEM (ZNST * ZSTAGE)   // 107520

__device__ __forceinline__ void znx_load(char* smbase, int st, int kc,
                                         int tid, int b, int c) {
    uint32_t so = smem_u32(smbase) + st * ZSTAGE;
    int kb = kc << 5;
    // A: 80 rows x 4 segs = 320 loads
    {
        int r = tid >> 2, s = tid & 3;
        size_t g = ((size_t)b * 80 + r) * KDIM + c * FF + kb + s * 8;
        cp16(so + r * ZROWB + (s << 4), g_nxh + g);
        if (tid < 64) {
            int idx2 = tid + 256;
            int r2 = idx2 >> 2, s2 = idx2 & 3;
            size_t g2 = ((size_t)b * 80 + r2) * KDIM + c * FF + kb + s2 * 8;
            cp16(so + r2 * ZROWB + (s2 << 4), g_nxh + g2);
        }
    }
    // B: 256 rows x 4 segs = 1024 loads (4 per thread)
    #pragma unroll
    for (int t = 0; t < 4; t++) {
        int idx = tid + (t << 8);
        int a = idx >> 2, s = idx & 3;
        size_t g = (((size_t)(b * CC + c)) * FF + a) * FF + kb + s * 8;
        cp16(so + ZA_TILE + a * ZROWB + (s << 4), g_adjh + g);
    }
}

__global__ __launch_bounds__(256, 1) void k_znx() {
    extern __shared__ char sm[];
    uint32_t sbase = smem_u32(sm);
    int tid = threadIdx.x;
    int lane = tid & 31, wid = tid >> 5;
    int c = blockIdx.x, b = blockIdx.y;
    int wn = wid << 5;             // 8 warps x N=32

    float acc[5][4][4];
    #pragma unroll
    for (int i = 0; i < 5; i++)
        #pragma unroll
        for (int j = 0; j < 4; j++)
            #pragma unroll
            for (int q = 0; q < 4; q++) acc[i][j][q] = 0.f;

    int a_row = ((lane >> 3) & 1) * 8 + (lane & 7);
    int a_kof = (lane >> 4) * 8;
    int b_row = wn + ((lane >> 4) & 1) * 8 + (lane & 7);
    int b_kof = ((lane >> 3) & 1) * 8;

    #pragma unroll
    for (int st = 0; st < 3; st++) {
        znx_load(sm, st, st, tid, b, c);
        asm volatile("cp.async.commit_group;" ::: "memory");
    }

    for (int kc = 0; kc < 8; kc++) {
        asm volatile("cp.async.wait_group 2;" ::: "memory");
        __syncthreads();
        if (kc + 3 < 8) znx_load(sm, (kc + 3) % ZNST, kc + 3, tid, b, c);
        asm volatile("cp.async.commit_group;" ::: "memory");

        uint32_t sA = sbase + (kc % ZNST) * ZSTAGE;
        uint32_t sB = sA + ZA_TILE;
        #pragma unroll
        for (int kk = 0; kk < 2; kk++) {
            int kb = kk << 4;
            uint32_t ah[5][4], bh[2][4];
            uint32_t aofs = a_row * ZROWB + (kb + a_kof) * 2;
            #pragma unroll
            for (int mt = 0; mt < 5; mt++)
                ldsm4(ah[mt], sA + aofs + mt * 16 * ZROWB);
            uint32_t bofs = b_row * ZROWB + (kb + b_kof) * 2;
            #pragma unroll
            for (int np = 0; np < 2; np++)
                ldsm4(bh[np], sB + bofs + np * 16 * ZROWB);
            #pragma unroll
            for (int mt = 0; mt < 5; mt++)
                #pragma unroll
                for (int j = 0; j < 4; j++)
                    mma16816h(acc[mt][j], ah[mt], &bh[j >> 1][(j & 1) * 2]);
        }
        __syncthreads();
    }

    // epilogue: rows = n (x at n==64), cols = a; write single fp16 Zh
    #pragma unroll
    for (int mt = 0; mt < 5; mt++) {
        #pragma unroll
        for (int half = 0; half < 2; half++) {
            int r = mt * 16 + (lane >> 2) + half * 8;
            int zr;
            if (r < 64)       zr = 64 + b * NN + r;
            else if (r == 64) zr = b;
            else continue;
            #pragma unroll
            for (int j = 0; j < 4; j++) {
                int col = c * FF + wn + j * 8 + (lane & 3) * 2;
                *(__half2*)(g_Zh + (size_t)zr * KDIM + col) =
                    __halves2half2(__float2half_rn(acc[mt][j][half * 2]),
                                   __float2half_rn(acc[mt][j][half * 2 + 1]));
            }
        }
    }
}

// ====================== K7: big GEMM, 96x128 tiles, occ 2 (proven) ======================
#define NST 5
#define ROWB 80
#define GM 96
#define A_TILE_B (GM * ROWB)          // 7680
#define B_TILE_B (128 * ROWB)         // 10240
#define STAGE_B (A_TILE_B + B_TILE_B) // 17920
#define GEMM_SMEM (NST * STAGE_B)     // 89600

__device__ __forceinline__ void g_load_stage(char* smembase, int st, int kc,
                                             int tid, int m0, int n0) {
    uint32_t so_base = smem_u32(smembase) + st * STAGE_B;
    {
        int row = tid >> 2, seg = tid & 3;
        size_t gA = (size_t)(m0 + row) * KDIM + (kc << 5) + (seg << 3);
        cp16(so_base + row * ROWB + (seg << 4), g_Zh + gA);
        if (tid < 128) {
            int idx = tid + 256;
            int row2 = idx >> 2, seg2 = idx & 3;
            size_t gA2 = (size_t)(m0 + row2) * KDIM + (kc << 5) + (seg2 << 3);
            cp16(so_base + row2 * ROWB + (seg2 << 4), g_Zh + gA2);
        }
    }
    #pragma unroll
    for (int t = 0; t < 2; t++) {
        int idx = tid + (t << 8);
        int row = idx >> 2, seg = idx & 3;
        size_t gB = (size_t)(n0 + row) * KDIM + (kc << 5) + (seg << 3);
        cp16(so_base + A_TILE_B + row * ROWB + (seg << 4), g_Wh + gB);
    }
}

__global__ __launch_bounds__(256, 2) void k_gemm_mma(float* __restrict__ out) {
    extern __shared__ char sm[];
    uint32_t sbase = smem_u32(sm);
    int tid = threadIdx.x;
    int lane = tid & 31, wid = tid >> 5;
    int m0 = blockIdx.y * GM, n0 = blockIdx.x << 7;
    int wm = (wid >> 2) * 48;       // 0 / 48 (3 m16 frags each)
    int wn = (wid & 3) << 5;

    float c[3][4][4];
    #pragma unroll
    for (int i = 0; i < 3; i++)
        #pragma unroll
        for (int j = 0; j < 4; j++)
            #pragma unroll
            for (int q = 0; q < 4; q++) c[i][j][q] = 0.f;

    int a_row = wm + ((lane >> 3) & 1) * 8 + (lane & 7);
    int a_kof = (lane >> 4) * 8;
    int b_row = wn + ((lane >> 4) & 1) * 8 + (lane & 7);
    int b_kof = ((lane >> 3) & 1) * 8;

    #pragma unroll
    for (int st = 0; st < 4; st++) {
        g_load_stage(sm, st, st, tid, m0, n0);
        asm volatile("cp.async.commit_group;" ::: "memory");
    }

    for (int kc = 0; kc < 64; kc++) {
        asm volatile("cp.async.wait_group 3;" ::: "memory");
        __syncthreads();
        if (kc + 4 < 64) g_load_stage(sm, (kc + 4) % NST, kc + 4, tid, m0, n0);
        asm volatile("cp.async.commit_group;" ::: "memory");

        uint32_t sA = sbase + (kc % NST) * STAGE_B;
        uint32_t sB = sA + A_TILE_B;
        #pragma unroll
        for (int kk = 0; kk < 2; kk++) {
            int kb = kk << 4;
            uint32_t ah[3][4], bh[2][4];
            uint32_t aofs = a_row * ROWB + (kb + a_kof) * 2;
            #pragma unroll
            for (int mt = 0; mt < 3; mt++)
                ldsm4(ah[mt], sA + aofs + mt * 16 * ROWB);
            uint32_t bofs = b_row * ROWB + (kb + b_kof) * 2;
            #pragma unroll
            for (int np = 0; np < 2; np++)
                ldsm4(bh[np], sB + bofs + np * 16 * ROWB);
            #pragma unroll
            for (int mt = 0; mt < 3; mt++)
                #pragma unroll
                for (int j = 0; j < 4; j++)
                    mma16816h(c[mt][j], ah[mt], &bh[j >> 1][(j & 1) * 2]);
        }
        __syncthreads();
    }

    #pragma unroll
    for (int mt = 0; mt < 3; mt++) {
        int r0 = m0 + wm + mt * 16 + (lane >> 2);
        #pragma unroll
        for (int j = 0; j < 4; j++) {
            int col = n0 + wn + j * 8 + (lane & 3) * 2;
            if (r0 < MROWS)
                *(float2*)(out + (size_t)r0 * ODIM + col) =
                    make_float2(c[mt][j][0], c[mt][j][1]);
            if (r0 + 8 < MROWS)
                *(float2*)(out + (size_t)(r0 + 8) * ODIM + col) =
                    make_float2(c[mt][j][2], c[mt][j][3]);
        }
    }
}

extern "C" void kernel_launch(void* const* d_in, const int* in_sizes, int n_in,
                              void* d_out, int out_size) {
    const float* x  = (const float*)d_in[0];  // (64,8,256)
    const float* nb = (const float*)d_in[1];  // (64,64,8,256)
    const float* W1 = (const float*)d_in[2];  // (8,256)
    const float* W2 = (const float*)d_in[3];  // (8,256)
    const float* Wc = (const float*)d_in[4];  // (2048,8,256)
    float* out = (float*)d_out;

    static bool attr_set = false;
    if (!attr_set) {
        cudaFuncSetAttribute(k_gemm_mma, cudaFuncAttributeMaxDynamicSharedMemorySize,
                             GEMM_SMEM);
        cudaFuncSetAttribute(k_znx, cudaFuncAttributeMaxDynamicSharedMemorySize,
                             ZNX_SMEM);
        attr_set = true;
    }

    k_prep<<<NB_PREP, 256>>>(x, nb, W1, W2, Wc);
    k_t<<<256, 256>>>();
    k_adj<<<dim3(FF / 4, BB), 256>>>(x);
    k_znx<<<dim3(CC, BB), 256, ZNX_SMEM>>>();
    k_gemm_mma<<<dim3(16, MPAD / GM), 256, GEMM_SMEM>>>(out);
}